// round 14
// baseline (speedup 1.0000x reference)
#include <cuda_runtime.h>
#include <cstdint>

// Problem constants
#define B_ 32
#define T_ 1024
#define D_ 256
#define H_ 256
#define NS 32                      // items per batch: 1024 items x 32 t-rows
#define OUT_CTAS 384               // bounded persistent grid for k_out (~2.6/SM)

// Scratch (allocation-free rule: __device__ globals)
__device__ float g_part[B_ * NS * D_];   // 1 MB of partial t-sums
__device__ float g_W[B_ * D_];
__device__ float g_bv[B_ * D_];

__device__ __forceinline__ float4 add4(float4 a, float4 b)
{
    return make_float4(a.x + b.x, a.y + b.y, a.z + b.z, a.w + b.w);
}

// ---------------------------------------------------------------------------
// Kernel 1: partial t-sums. grid 1024, block 256 (best measured shape).
// Item w = 32 consecutive t-rows. Thread (tx in [0,64): d4, ty in [0,4)):
// 8 front-batched independent LDG.128.
// Entry trigger: lets k_mlp launch now (only 64 CTAs; they prefetch weights).
// ---------------------------------------------------------------------------
__global__ void __launch_bounds__(256) k_reduce(const float* __restrict__ x)
{
    cudaTriggerProgrammaticLaunchCompletion();

    const int w  = blockIdx.x;
    const int tx = threadIdx.x & 63;
    const int ty = threadIdx.x >> 6;

    const float4* xp = reinterpret_cast<const float4*>(x) + (size_t)w * (32 * 64);

    float4 v[8];
#pragma unroll
    for (int k = 0; k < 8; k++)
        v[k] = xp[(ty + 4 * k) * 64 + tx];

    float4 s0 = add4(add4(v[0], v[1]), add4(v[2], v[3]));
    float4 s1 = add4(add4(v[4], v[5]), add4(v[6], v[7]));
    float4 acc = add4(s0, s1);

    __shared__ float4 sm[4][64];
    sm[ty][tx] = acc;
    __syncthreads();
    if (ty == 0) {
        float4 r = add4(add4(sm[0][tx], sm[1][tx]), add4(sm[2][tx], sm[3][tx]));
        reinterpret_cast<float4*>(g_part)[w * 64 + tx] = r;
    }
}

// ---------------------------------------------------------------------------
// Kernel 2: the two MLPs. grid (B, 2), block 256.
// Pre-sync (overlaps reduce): warm the 1 MB of weights into L2.
// Entry trigger: lets k_out launch now (bounded 384-CTA grid with productive
// pre-sync work).
// ---------------------------------------------------------------------------
__global__ void __launch_bounds__(256) k_mlp(
    const int* __restrict__ len,
    const float* __restrict__ w1w, const float* __restrict__ w1b,
    const float* __restrict__ w2w, const float* __restrict__ w2b,
    const float* __restrict__ v1w, const float* __restrict__ v1b,
    const float* __restrict__ v2w, const float* __restrict__ v2b)
{
    cudaTriggerProgrammaticLaunchCompletion();

    const int b   = blockIdx.x;
    const int sel = blockIdx.y;
    const float* W1 = sel ? v1w : w1w;
    const float* B1 = sel ? v1b : w1b;
    const float* W2 = sel ? v2w : w2w;
    const float* B2 = sel ? v2b : w2b;

    const int j = threadIdx.x;

    // ---- pre-sync: warm the 4 weight matrices (4 x 2048 lines of 128B) ----
    {
        const int ctaid = b * 2 + sel;               // 0..63
        const int idx   = ctaid * 128 + (j >> 1);    // 8192 lines, 2 thr/line
        const int mat   = idx >> 11;                 // 0..3
        const int line  = idx & 2047;
        const float* bases[4] = { w1w, w2w, v1w, v2w };
        const char* p = (const char*)bases[mat] + (size_t)line * 128;
        asm volatile("prefetch.global.L2 [%0];" :: "l"(p));
    }

    cudaGridDependencySynchronize();   // wait for k_reduce results

    __shared__ float c[D_];
    __shared__ float h[H_];

    // finalize mean (partials L2-resident)
    {
        float s = 0.f;
#pragma unroll
        for (int p = 0; p < NS; p++)
            s += g_part[(b * NS + p) * D_ + j];
        c[j] = s / (float)__ldg(&len[b]);
    }
    __syncthreads();

    // layer 1
    {
        const float4* row = reinterpret_cast<const float4*>(W1 + (size_t)j * D_);
        const float4* cv  = reinterpret_cast<const float4*>(c);
        float acc = B1[j];
#pragma unroll 8
        for (int i = 0; i < D_ / 4; i++) {
            float4 w = row[i], cc = cv[i];
            acc += w.x * cc.x + w.y * cc.y + w.z * cc.z + w.w * cc.w;
        }
        h[j] = 0.5f * acc * (1.f + erff(acc * 0.70710678118654752f));  // exact gelu
    }
    __syncthreads();

    // layer 2
    {
        const float4* row = reinterpret_cast<const float4*>(W2 + (size_t)j * H_);
        const float4* hv  = reinterpret_cast<const float4*>(h);
        float acc = B2[j];
#pragma unroll 8
        for (int i = 0; i < H_ / 4; i++) {
            float4 w = row[i], hh = hv[i];
            acc += w.x * hh.x + w.y * hh.y + w.z * hh.z + w.w * hh.w;
        }
        (sel ? g_bv : g_W)[b * D_ + j] = acc;
    }
}

// ---------------------------------------------------------------------------
// Kernel 3: persistent elementwise output. grid OUT_CTAS, block 256 (8 warps).
// Pre-sync (overlaps reduce/mlp): store zeros for ALL invalid rows (t >= L)
// — no MLP dependency. Post-sync: valid rows, warp-per-row, 2 rows per
// iteration -> 4 front-batched LDG.128 per lane.
// ---------------------------------------------------------------------------
__global__ void __launch_bounds__(256) k_out(
    const float* __restrict__ x,
    const int* __restrict__ len,
    float* __restrict__ out)
{
    const int wid  = threadIdx.x >> 5;
    const int lane = threadIdx.x & 31;
    const int gw   = blockIdx.x * 8 + wid;        // global warp id
    const int NW   = OUT_CTAS * 8;                // total warps

    __shared__ int sl[B_];
    if (threadIdx.x < B_) sl[threadIdx.x] = len[threadIdx.x];
    __syncthreads();

    const float4* x4 = reinterpret_cast<const float4*>(x);
    float4*       o4 = reinterpret_cast<float4*>(out);
    const float4  z  = make_float4(0.f, 0.f, 0.f, 0.f);

    // ---- pre-sync: zero all invalid rows (independent of MLP) ----
    for (int r = gw; r < B_ * T_; r += NW) {
        const int t = r & (T_ - 1);
        const int b = r >> 10;
        if (t >= sl[b]) {
            const size_t i0 = (size_t)r * 64 + lane;
            o4[i0]      = z;
            o4[i0 + 32] = z;
        }
    }

    cudaGridDependencySynchronize();   // wait for g_W / g_bv

    // ---- post-sync: valid rows, 2 rows per iteration for ILP ----
    for (int r = gw; r < B_ * T_; r += 2 * NW) {
        const int r2 = r + NW;

        const int t1 = r & (T_ - 1),  b1 = r >> 10;
        const bool v1 = (t1 < sl[b1]);
        const int t2 = r2 < B_ * T_ ? (r2 & (T_ - 1)) : 0;
        const int b2 = r2 < B_ * T_ ? (r2 >> 10) : 0;
        const bool v2 = (r2 < B_ * T_) && (t2 < sl[b2]);

        const size_t i1 = (size_t)r  * 64 + lane;
        const size_t i2 = (size_t)r2 * 64 + lane;

        // front-batched loads (up to 4 independent LDG.128)
        float4 xa1, xb1, xa2, xb2;
        if (v1) { xa1 = x4[i1]; xb1 = x4[i1 + 32]; }
        if (v2) { xa2 = x4[i2]; xb2 = x4[i2 + 32]; }

        if (v1) {
            float4 wa = reinterpret_cast<const float4*>(g_W)[b1 * 64 + lane];
            float4 wb = reinterpret_cast<const float4*>(g_W)[b1 * 64 + lane + 32];
            float4 va, vb;
            va.x = (1.f + wa.x) * xa1.x;  va.y = (1.f + wa.y) * xa1.y;
            va.z = (1.f + wa.z) * xa1.z;  va.w = (1.f + wa.w) * xa1.w;
            vb.x = (1.f + wb.x) * xb1.x;  vb.y = (1.f + wb.y) * xb1.y;
            vb.z = (1.f + wb.z) * xb1.z;  vb.w = (1.f + wb.w) * xb1.w;
            if (t1 == 0) {
                float4 ba = reinterpret_cast<const float4*>(g_bv)[b1 * 64 + lane];
                float4 bb = reinterpret_cast<const float4*>(g_bv)[b1 * 64 + lane + 32];
                va = add4(va, ba);  vb = add4(vb, bb);
            }
            o4[i1]      = va;
            o4[i1 + 32] = vb;
        }
        if (v2) {
            float4 wa = reinterpret_cast<const float4*>(g_W)[b2 * 64 + lane];
            float4 wb = reinterpret_cast<const float4*>(g_W)[b2 * 64 + lane + 32];
            float4 va, vb;
            va.x = (1.f + wa.x) * xa2.x;  va.y = (1.f + wa.y) * xa2.y;
            va.z = (1.f + wa.z) * xa2.z;  va.w = (1.f + wa.w) * xa2.w;
            vb.x = (1.f + wb.x) * xb2.x;  vb.y = (1.f + wb.y) * xb2.y;
            vb.z = (1.f + wb.z) * xb2.z;  vb.w = (1.f + wb.w) * xb2.w;
            if (t2 == 0) {
                float4 ba = reinterpret_cast<const float4*>(g_bv)[b2 * 64 + lane];
                float4 bb = reinterpret_cast<const float4*>(g_bv)[b2 * 64 + lane + 32];
                va = add4(va, ba);  vb = add4(vb, bb);
            }
            o4[i2]      = va;
            o4[i2 + 32] = vb;
        }
    }
}

// ---------------------------------------------------------------------------
extern "C" void kernel_launch(void* const* d_in, const int* in_sizes, int n_in,
                              void* d_out, int out_size)
{
    const float* x    = (const float*)d_in[0];
    const int*   len  = (const int*)  d_in[1];
    const float* w1w  = (const float*)d_in[2];
    const float* w1b  = (const float*)d_in[3];
    const float* w2w  = (const float*)d_in[4];
    const float* w2b  = (const float*)d_in[5];
    const float* v1w  = (const float*)d_in[6];
    const float* v1b  = (const float*)d_in[7];
    const float* v2w  = (const float*)d_in[8];
    const float* v2b  = (const float*)d_in[9];
    float* out = (float*)d_out;

    // Kernel 1: normal launch
    k_reduce<<<B_ * NS, 256>>>(x);

    // PDL attribute for the two dependent kernels
    cudaLaunchAttribute pdl;
    pdl.id = cudaLaunchAttributeProgrammaticStreamSerialization;
    pdl.val.programmaticStreamSerializationAllowed = 1;

    // Kernel 2: mlp (PDL secondary of k_reduce; launches at reduce's entry)
    {
        cudaLaunchConfig_t cfg = {};
        cfg.gridDim  = dim3(B_, 2);
        cfg.blockDim = dim3(256);
        cfg.attrs    = &pdl;
        cfg.numAttrs = 1;
        cudaLaunchKernelEx(&cfg, k_mlp, len, w1w, w1b, w2w, w2b,
                           v1w, v1b, v2w, v2b);
    }

    // Kernel 3: out (PDL secondary of k_mlp; launches at mlp's entry;
    // bounded persistent grid, productive pre-sync work)
    {
        cudaLaunchConfig_t cfg = {};
        cfg.gridDim  = dim3(OUT_CTAS);
        cfg.blockDim = dim3(256);
        cfg.attrs    = &pdl;
        cfg.numAttrs = 1;
        cudaLaunchKernelEx(&cfg, k_out, x, len, out);
    }
}

// round 17
// speedup vs baseline: 1.0593x; 1.0593x over previous
#include <cuda_runtime.h>
#include <cstdint>

// Problem constants
#define B_ 32
#define T_ 1024
#define D_ 256
#define H_ 256
#define NS 32                      // items per batch: 1024 items x 32 t-rows

// Scratch (allocation-free rule: __device__ globals)
__device__ float g_part[B_ * NS * D_];   // 1 MB of partial t-sums
__device__ float g_W[B_ * D_];
__device__ float g_bv[B_ * D_];

__device__ __forceinline__ float4 add4(float4 a, float4 b)
{
    return make_float4(a.x + b.x, a.y + b.y, a.z + b.z, a.w + b.w);
}

// ---------------------------------------------------------------------------
// Kernel 1: partial t-sums. grid 1024, block 256 (best measured shape).
// Item w = 32 consecutive t-rows. Thread (tx in [0,64): d4, ty in [0,4)):
// 8 front-batched independent LDG.128.
// Entry trigger: lets k_mlp (64 CTAs, productive weight-prefetch) start early.
// ---------------------------------------------------------------------------
__global__ void __launch_bounds__(256) k_reduce(const float* __restrict__ x)
{
    cudaTriggerProgrammaticLaunchCompletion();

    const int w  = blockIdx.x;
    const int tx = threadIdx.x & 63;
    const int ty = threadIdx.x >> 6;

    const float4* xp = reinterpret_cast<const float4*>(x) + (size_t)w * (32 * 64);

    float4 v[8];
#pragma unroll
    for (int k = 0; k < 8; k++)
        v[k] = xp[(ty + 4 * k) * 64 + tx];

    float4 s0 = add4(add4(v[0], v[1]), add4(v[2], v[3]));
    float4 s1 = add4(add4(v[4], v[5]), add4(v[6], v[7]));
    float4 acc = add4(s0, s1);

    __shared__ float4 sm[4][64];
    sm[ty][tx] = acc;
    __syncthreads();
    if (ty == 0) {
        float4 r = add4(add4(sm[0][tx], sm[1][tx]), add4(sm[2][tx], sm[3][tx]));
        reinterpret_cast<float4*>(g_part)[w * 64 + tx] = r;
    }
}

// ---------------------------------------------------------------------------
// Kernel 2: the two MLPs. grid (B, 2), block 256.
// Pre-sync (overlaps reduce tail): warm the 1 MB of weights into L2.
// NO entry trigger -> k_out launches only at mlp completion (R10 semantics;
// R11/R14 proved early k_out co-residency poisons the reduce phase).
// ---------------------------------------------------------------------------
__global__ void __launch_bounds__(256) k_mlp(
    const int* __restrict__ len,
    const float* __restrict__ w1w, const float* __restrict__ w1b,
    const float* __restrict__ w2w, const float* __restrict__ w2b,
    const float* __restrict__ v1w, const float* __restrict__ v1b,
    const float* __restrict__ v2w, const float* __restrict__ v2b)
{
    const int b   = blockIdx.x;
    const int sel = blockIdx.y;
    const float* W1 = sel ? v1w : w1w;
    const float* B1 = sel ? v1b : w1b;
    const float* W2 = sel ? v2w : w2w;
    const float* B2 = sel ? v2b : w2b;

    const int j = threadIdx.x;

    // ---- pre-sync: warm the 4 weight matrices (4 x 2048 lines of 128B) ----
    {
        const int ctaid = b * 2 + sel;               // 0..63
        const int idx   = ctaid * 128 + (j >> 1);    // 8192 lines, 2 thr/line
        const int mat   = idx >> 11;                 // 0..3
        const int line  = idx & 2047;
        const float* bases[4] = { w1w, w2w, v1w, v2w };
        const char* p = (const char*)bases[mat] + (size_t)line * 128;
        asm volatile("prefetch.global.L2 [%0];" :: "l"(p));
    }

    cudaGridDependencySynchronize();   // wait for k_reduce results

    __shared__ float c[D_];
    __shared__ float h[H_];

    // finalize mean (partials L2-resident)
    {
        float s = 0.f;
#pragma unroll
        for (int p = 0; p < NS; p++)
            s += g_part[(b * NS + p) * D_ + j];
        c[j] = s / (float)__ldg(&len[b]);
    }
    __syncthreads();

    // layer 1
    {
        const float4* row = reinterpret_cast<const float4*>(W1 + (size_t)j * D_);
        const float4* cv  = reinterpret_cast<const float4*>(c);
        float acc = B1[j];
#pragma unroll 8
        for (int i = 0; i < D_ / 4; i++) {
            float4 w = row[i], cc = cv[i];
            acc += w.x * cc.x + w.y * cc.y + w.z * cc.z + w.w * cc.w;
        }
        h[j] = 0.5f * acc * (1.f + erff(acc * 0.70710678118654752f));  // exact gelu
    }
    __syncthreads();

    // layer 2
    {
        const float4* row = reinterpret_cast<const float4*>(W2 + (size_t)j * H_);
        const float4* hv  = reinterpret_cast<const float4*>(h);
        float acc = B2[j];
#pragma unroll 8
        for (int i = 0; i < H_ / 4; i++) {
            float4 w = row[i], hh = hv[i];
            acc += w.x * hh.x + w.y * hh.y + w.z * hh.z + w.w * hh.w;
        }
        (sel ? g_bv : g_W)[b * D_ + j] = acc;
    }
}

// ---------------------------------------------------------------------------
// Kernel 3: elementwise output, warp-per-4-rows. grid 1024, block 256.
// Rows r0..r0+3 are 4-aligned -> all share one b (T=1024 divisible by 4):
//   * (1+W[b,:]) loaded ONCE per group (amortized 4x)
//   * 8 front-batched independent LDG.128 per lane (was 2) -> latency hidden
// Pre-sync: x loads (independent of mlp). Post-sync: scale + store.
// out[b,t,d] = (t<L) ? (1+W[b,d])*x[b,t,d] + (t==0 ? bv[b,d] : 0) : 0
// ---------------------------------------------------------------------------
__global__ void __launch_bounds__(256) k_out(
    const float* __restrict__ x,
    const int* __restrict__ len,
    float* __restrict__ out)
{
    const int wid  = threadIdx.x >> 5;
    const int lane = threadIdx.x & 31;
    const int r0   = (blockIdx.x * 8 + wid) * 4;   // first of 4 rows
    const int b    = r0 >> 10;                     // same b for all 4 rows
    const int t0   = r0 & (T_ - 1);

    const float4* x4 = reinterpret_cast<const float4*>(x);
    float4*       o4 = reinterpret_cast<float4*>(out);

    const int L  = __ldg(&len[b]);
    const int nv = min(max(L - t0, 0), 4);         // rows valid in this group

    // ---- pre-sync: front-batched x loads (up to 8 independent LDG.128) ----
    float4 xa[4], xb[4];
#pragma unroll
    for (int i = 0; i < 4; i++) {
        if (i < nv) {
            const size_t idx = (size_t)(r0 + i) * 64 + lane;
            xa[i] = x4[idx];
            xb[i] = x4[idx + 32];
        }
    }

    cudaGridDependencySynchronize();   // wait for g_W / g_bv

    // one (1+W) fetch per group
    float4 wa = reinterpret_cast<const float4*>(g_W)[b * 64 + lane];
    float4 wb = reinterpret_cast<const float4*>(g_W)[b * 64 + lane + 32];
    wa.x += 1.f; wa.y += 1.f; wa.z += 1.f; wa.w += 1.f;
    wb.x += 1.f; wb.y += 1.f; wb.z += 1.f; wb.w += 1.f;

    const float4 z = make_float4(0.f, 0.f, 0.f, 0.f);

#pragma unroll
    for (int i = 0; i < 4; i++) {
        const size_t idx = (size_t)(r0 + i) * 64 + lane;
        if (i < nv) {
            float4 va, vb;
            va.x = wa.x * xa[i].x;  va.y = wa.y * xa[i].y;
            va.z = wa.z * xa[i].z;  va.w = wa.w * xa[i].w;
            vb.x = wb.x * xb[i].x;  vb.y = wb.y * xb[i].y;
            vb.z = wb.z * xb[i].z;  vb.w = wb.w * xb[i].w;
            if (t0 + i == 0) {     // only ever true for i==0 of the first group
                float4 ba = reinterpret_cast<const float4*>(g_bv)[b * 64 + lane];
                float4 bb = reinterpret_cast<const float4*>(g_bv)[b * 64 + lane + 32];
                va = add4(va, ba);
                vb = add4(vb, bb);
            }
            o4[idx]      = va;
            o4[idx + 32] = vb;
        } else {
            o4[idx]      = z;
            o4[idx + 32] = z;
        }
    }
}

// ---------------------------------------------------------------------------
extern "C" void kernel_launch(void* const* d_in, const int* in_sizes, int n_in,
                              void* d_out, int out_size)
{
    const float* x    = (const float*)d_in[0];
    const int*   len  = (const int*)  d_in[1];
    const float* w1w  = (const float*)d_in[2];
    const float* w1b  = (const float*)d_in[3];
    const float* w2w  = (const float*)d_in[4];
    const float* w2b  = (const float*)d_in[5];
    const float* v1w  = (const float*)d_in[6];
    const float* v1b  = (const float*)d_in[7];
    const float* v2w  = (const float*)d_in[8];
    const float* v2b  = (const float*)d_in[9];
    float* out = (float*)d_out;

    // Kernel 1: normal launch (entry trigger inside, for mlp only)
    k_reduce<<<B_ * NS, 256>>>(x);

    // PDL attribute for the two dependent kernels
    cudaLaunchAttribute pdl;
    pdl.id = cudaLaunchAttributeProgrammaticStreamSerialization;
    pdl.val.programmaticStreamSerializationAllowed = 1;

    // Kernel 2: mlp (launches at reduce's entry trigger; prefetches weights)
    {
        cudaLaunchConfig_t cfg = {};
        cfg.gridDim  = dim3(B_, 2);
        cfg.blockDim = dim3(256);
        cfg.attrs    = &pdl;
        cfg.numAttrs = 1;
        cudaLaunchKernelEx(&cfg, k_mlp, len, w1w, w1b, w2w, w2b,
                           v1w, v1b, v2w, v2b);
    }

    // Kernel 3: out (mlp has NO entry trigger -> launches at mlp completion,
    // hiding only launch latency; proven-safe R10 semantics)
    {
        cudaLaunchConfig_t cfg = {};
        cfg.gridDim  = dim3(B_ * T_ / 32);   // 1024 CTAs, warp-per-4-rows
        cfg.blockDim = dim3(256);
        cfg.attrs    = &pdl;
        cfg.numAttrs = 1;
        cudaLaunchKernelEx(&cfg, k_out, x, len, out);
    }
}